// round 10
// baseline (speedup 1.0000x reference)
#include <cuda_runtime.h>
#include <cuda_fp16.h>
#include <cstdint>

// TopKNoisyRouter: fused dual GEMM [N,1024]x[1024,128], fp16 2-way split
// (3 HMMA products, fp32 accum, W pre-scaled by 32).
// WARP-SPECIALIZED: 12 warps/CTA = 8 consumer (MMA) + 4 producer
// (x LDG -> split -> STS, B cp.async). 3-stage A+B ring, named-barrier
// full/empty protocol (ids 1..3 full, 4..6 empty, count 384). Consumers
// never hit __syncthreads in the mainloop. occ 1. Fused top-2 epilogue.

#define DK 1024
#define NE 64
#define BM 128
#define KC 32
#define NCHUNK (DK / KC)      // 32
#define PLANE 8192            // 128 rows x 32 fp16 (64B rows)
#define STAGE_B 32768         // Ah, Al, Bh, Bl planes
#define NSTAGE 3
#define NTHREADS 384
#define SMEM_BYTES 100352     // max(3*STAGE 96KB, epilogue 100KB)

__device__ __half g_w[2][128 * DK];   // fp16(32w), fp16(32w - hi); K-major

__device__ __forceinline__ uint32_t smem_u32(const void* p) {
    uint32_t a;
    asm("{ .reg .u64 t; cvta.to.shared.u64 t, %1; cvt.u32.u64 %0, t; }" : "=r"(a) : "l"(p));
    return a;
}
__device__ __forceinline__ uint32_t swz32(uint32_t r, uint32_t c) {
    return (r >> 1) * 128 + (r & 1) * 64 + (c ^ (((r >> 1) & 3) << 4));
}
__device__ __forceinline__ void cp16(uint32_t dst, const void* src) {
    asm volatile("cp.async.cg.shared.global [%0], [%1], 16;" :: "r"(dst), "l"(src));
}
__device__ __forceinline__ void bar_sync(int id) {
    asm volatile("bar.sync %0, %1;" :: "r"(id), "r"(NTHREADS) : "memory");
}
__device__ __forceinline__ void bar_arrive(int id) {
    asm volatile("bar.arrive %0, %1;" :: "r"(id), "r"(NTHREADS) : "memory");
}
__device__ __forceinline__ void ldsm4(uint32_t& r0, uint32_t& r1, uint32_t& r2,
                                      uint32_t& r3, uint32_t addr) {
    asm volatile("ldmatrix.sync.aligned.m8n8.x4.shared.b16 {%0,%1,%2,%3}, [%4];"
                 : "=r"(r0), "=r"(r1), "=r"(r2), "=r"(r3) : "r"(addr));
}
__device__ __forceinline__ void mma16816(float* c, const uint32_t* a,
                                         uint32_t b0, uint32_t b1) {
    asm volatile("mma.sync.aligned.m16n8k16.row.col.f32.f16.f16.f32 "
                 "{%0,%1,%2,%3}, {%4,%5,%6,%7}, {%8,%9}, {%0,%1,%2,%3};"
                 : "+f"(c[0]), "+f"(c[1]), "+f"(c[2]), "+f"(c[3])
                 : "r"(a[0]), "r"(a[1]), "r"(a[2]), "r"(a[3]), "r"(b0), "r"(b1));
}
__device__ __forceinline__ float softplusf(float v) {
    return fmaxf(v, 0.0f) + log1pf(expf(-fabsf(v)));
}
__device__ __forceinline__ uint32_t pack_h2(__half lo, __half hi) {
    return (uint32_t)__half_as_ushort(lo) | ((uint32_t)__half_as_ushort(hi) << 16);
}

__global__ void prep_weights(const float* __restrict__ wr, const float* __restrict__ wn) {
    int i = blockIdx.x * blockDim.x + threadIdx.x;    // 0 .. 128*1024-1
    int e = i >> 10, k = i & 1023;
    float v = 32.0f * ((e < NE) ? wr[e * DK + k] : wn[(e - NE) * DK + k]);
    __half h = __float2half_rn(v);
    g_w[0][i] = h;
    g_w[1][i] = __float2half_rn(v - __half2float(h));
}

__global__ __launch_bounds__(NTHREADS, 1)
void router_gemm(const float* __restrict__ x, const float* __restrict__ eps,
                 float* __restrict__ out, float* __restrict__ idx_out, int write_idx)
{
    extern __shared__ char smem[];
    const uint32_t sb = smem_u32(smem);
    const int tid = threadIdx.x;
    const int lane = tid & 31, wid = tid >> 5;
    const int row0 = blockIdx.x * BM;

    // coalesced zero-fill of this block's output tile [128 x 64]
    {
        float4 z = make_float4(0.f, 0.f, 0.f, 0.f);
        float4* ot = (float4*)(out + (size_t)row0 * NE);
        for (int u = tid; u < BM * NE / 4; u += NTHREADS) ot[u] = z;
    }

    float acc[4][4][4];   // consumer accumulators (dead for producers)
    const int wm = wid & 1, wq = wid >> 1;

    if (wid >= 8) {
        // ================= PRODUCER warps (tid 256..383) =================
        const int p = tid - 256;                 // 0..127: one x row each
        const float* xb = x + (size_t)(row0 + p) * DK;
        const uint32_t rowX = (uint32_t)((p >> 1) * 128 + (p & 1) * 64);
        const uint32_t xorX = (uint32_t)(((p >> 1) & 3) << 4);

        float4 xr[8];
        #pragma unroll
        for (int i = 0; i < 8; ++i) xr[i] = *(const float4*)(xb + 4 * i);

        #pragma unroll 1
        for (int c = 0; c < NCHUNK; ++c) {
            const int s = c % NSTAGE;
            if (c >= NSTAGE) bar_sync(4 + s);     // stage free?

            char* As = smem + (uint32_t)s * STAGE_B;
            // convert this chunk's row (32 fp32 -> 2 fp16 planes)
            #pragma unroll
            for (int i = 0; i < 8; ++i) {
                const uint32_t sw = rowX + (((uint32_t)(8 * i)) ^ xorX);
                float f[4] = {xr[i].x, xr[i].y, xr[i].z, xr[i].w};
                __half hh[4], hl[4];
                #pragma unroll
                for (int j = 0; j < 4; ++j) {
                    hh[j] = __float2half_rn(f[j]);
                    hl[j] = __float2half_rn(f[j] - __half2float(hh[j]));
                }
                *(uint2*)(As + sw)         = make_uint2(pack_h2(hh[0], hh[1]), pack_h2(hh[2], hh[3]));
                *(uint2*)(As + PLANE + sw) = make_uint2(pack_h2(hl[0], hl[1]), pack_h2(hl[2], hl[3]));
            }
            // prefetch next chunk's x (used next iteration; latency hidden)
            if (c + 1 < NCHUNK) {
                const float* xn = xb + (c + 1) * KC;
                #pragma unroll
                for (int i = 0; i < 8; ++i) xr[i] = *(const float4*)(xn + 4 * i);
            }
            // B tiles for this chunk via cp.async (1024 cp16 / 128 threads)
            const int k0 = c * KC;
            #pragma unroll
            for (int j = 0; j < 8; ++j) {
                const int u = p + 128 * j;       // 0..1023
                const int sp = u >> 9, rem = u & 511;
                const int n = rem >> 2, cu = (rem & 3) * 16;
                cp16(sb + (uint32_t)s * STAGE_B + 16384 + (uint32_t)sp * PLANE + swz32(n, cu),
                     &g_w[sp][n * DK + k0 + (cu >> 1)]);
            }
            asm volatile("cp.async.commit_group;" ::: "memory");
            asm volatile("cp.async.wait_group 0;" ::: "memory");
            bar_arrive(1 + s);                    // stage full
        }
    } else {
        // ================= CONSUMER warps (tid 0..255) =================
        const int rA = wm * 64 + (lane & 15);
        const uint32_t rowA = (uint32_t)((rA >> 1) * 128 + (rA & 1) * 64);
        const uint32_t xorA = (uint32_t)(((rA >> 1) & 3) << 4);
        const uint32_t cbA  = (uint32_t)((lane >> 4) * 16);
        const int rB = wq * 32 + (lane & 7) + ((lane >> 4) << 3);
        const uint32_t rowB = (uint32_t)((rB >> 1) * 128 + (rB & 1) * 64);
        const uint32_t xorB = (uint32_t)(((rB >> 1) & 3) << 4);
        const uint32_t cbB  = (uint32_t)(((lane >> 3) & 1) * 16);

        #pragma unroll
        for (int mt = 0; mt < 4; ++mt)
            #pragma unroll
            for (int nt = 0; nt < 4; ++nt)
                #pragma unroll
                for (int q = 0; q < 4; ++q) acc[mt][nt][q] = 0.f;

        #pragma unroll 1
        for (int c = 0; c < NCHUNK; ++c) {
            const int s = c % NSTAGE;
            bar_sync(1 + s);                      // stage full?

            const uint32_t stg = sb + (uint32_t)s * STAGE_B;
            const uint32_t Ah = stg, Al = stg + PLANE;
            const uint32_t Bh = stg + 16384, Bl = stg + 24576;

            #pragma unroll
            for (int ks = 0; ks < 2; ++ks) {
                const uint32_t kb = (uint32_t)(ks * 32);
                const uint32_t ca = (kb + cbA) ^ xorA;
                const uint32_t cc = (kb + cbB) ^ xorB;
                uint32_t a[4][4], bh[8], bl[8];
                #pragma unroll
                for (int mt = 0; mt < 4; ++mt)
                    ldsm4(a[mt][0], a[mt][1], a[mt][2], a[mt][3], Ah + rowA + mt * 1024 + ca);
                ldsm4(bh[0], bh[1], bh[2], bh[3], Bh + rowB + cc);
                ldsm4(bh[4], bh[5], bh[6], bh[7], Bh + rowB + 1024 + cc);
                ldsm4(bl[0], bl[1], bl[2], bl[3], Bl + rowB + cc);
                ldsm4(bl[4], bl[5], bl[6], bl[7], Bl + rowB + 1024 + cc);
                #pragma unroll
                for (int mt = 0; mt < 4; ++mt)
                    #pragma unroll
                    for (int nt = 0; nt < 4; ++nt)
                        mma16816(acc[mt][nt], a[mt], bh[2 * nt], bh[2 * nt + 1]);
                #pragma unroll
                for (int mt = 0; mt < 4; ++mt)
                    #pragma unroll
                    for (int nt = 0; nt < 4; ++nt)
                        mma16816(acc[mt][nt], a[mt], bl[2 * nt], bl[2 * nt + 1]);
                #pragma unroll
                for (int mt = 0; mt < 4; ++mt)
                    ldsm4(a[mt][0], a[mt][1], a[mt][2], a[mt][3], Al + rowA + mt * 1024 + ca);
                #pragma unroll
                for (int mt = 0; mt < 4; ++mt)
                    #pragma unroll
                    for (int nt = 0; nt < 4; ++nt)
                        mma16816(acc[mt][nt], a[mt], bh[2 * nt], bh[2 * nt + 1]);
            }
            bar_arrive(4 + s);                    // stage empty
        }
    }
    __syncthreads();   // all 384: GEMM done, smem free for epilogue reuse

    // ---- stage C (scaled 1/32, consumers) + eps (all), fused top-2 ----
    float* Cs = (float*)smem;                    // [128][130]
    float* Es = (float*)(smem + 66560);          // [128][66]
    if (wid < 8) {
        const float INV32 = 0.03125f;
        const int crow = wm * 64 + (lane >> 2);
        const int ccol = wq * 32 + (lane & 3) * 2;
        #pragma unroll
        for (int mt = 0; mt < 4; ++mt)
            #pragma unroll
            for (int nt = 0; nt < 4; ++nt) {
                float* p0 = Cs + (crow + mt * 16) * 130 + ccol + nt * 8;
                p0[0] = acc[mt][nt][0] * INV32; p0[1] = acc[mt][nt][1] * INV32;
                float* p1 = p0 + 8 * 130;
                p1[0] = acc[mt][nt][2] * INV32; p1[1] = acc[mt][nt][3] * INV32;
            }
    }
    {
        const float4* eg = (const float4*)(eps + (size_t)row0 * NE);
        for (int u = tid; u < BM * NE / 4; u += NTHREADS) {
            float4 v = eg[u];
            int r = u >> 4, e = (u & 15) * 4;
            float* d = Es + r * 66 + e;
            d[0] = v.x; d[1] = v.y; d[2] = v.z; d[3] = v.w;
        }
    }
    __syncthreads();

    if (tid < BM) {
        const int r = tid;
        const size_t n = (size_t)row0 + r;
        const float* lg = Cs + r * 130;
        const float* er = Es + r * 66;
        const float NEG = __int_as_float(0xff800000);
        float m1 = NEG, m2 = NEG; int i1 = 0, i2 = 0;
        #pragma unroll
        for (int e = 0; e < NE; ++e) {
            float v = lg[e] + er[e] * softplusf(lg[e + 64]);
            if (v > m1) { m2 = m1; i2 = i1; m1 = v; i1 = e; }
            else if (v > m2) { m2 = v; i2 = e; }
        }
        float ee = expf(m2 - m1);
        float inv = 1.0f / (1.0f + ee);
        out[n * NE + i1] = inv;
        out[n * NE + i2] = ee * inv;
        if (write_idx) {
            idx_out[n * 2 + 0] = (float)i1;
            idx_out[n * 2 + 1] = (float)i2;
        }
    }
}

extern "C" void kernel_launch(void* const* d_in, const int* in_sizes, int n_in,
                              void* d_out, int out_size)
{
    const float* x   = (const float*)d_in[0];
    const float* wr  = (const float*)d_in[1];
    const float* wn  = (const float*)d_in[2];
    const float* eps = (const float*)d_in[3];
    float* out = (float*)d_out;

    const int N = in_sizes[3] / NE;
    const int write_idx = (out_size >= N * NE + N * 2) ? 1 : 0;
    float* idx_out = out + (size_t)N * NE;

    prep_weights<<<(128 * DK) / 256, 256>>>(wr, wn);

    cudaFuncSetAttribute(router_gemm,
                         cudaFuncAttributeMaxDynamicSharedMemorySize, SMEM_BYTES);
    router_gemm<<<N / BM, NTHREADS, SMEM_BYTES>>>(x, eps, out, idx_out, write_idx);
}

// round 11
// speedup vs baseline: 1.5644x; 1.5644x over previous
#include <cuda_runtime.h>
#include <cuda_fp16.h>
#include <cstdint>

// TopKNoisyRouter: fused dual GEMM [N,1024]x[1024,128], fp16 2-way split
// (3 HMMA products, fp32 accum, W pre-scaled by 32). Round-9 buffers
// (A 2-buf, B 3-buf ring, cp.async distance 2), chunk order restructured:
//   wait_group 1 -> __syncthreads -> issue B(c+2) -> MMA(c) -> convert(c+1)
// so the fp32->fp16 convert rides BEHIND the MMA in each warp instead of
// convoying in front of the barrier. Packed f16x2 converts + STS.128.
// 2 CTAs/SM. Fused noisy-top-2 + softmax epilogue.

#define DK 1024
#define NE 64
#define BM 128
#define KC 32
#define NCHUNK (DK / KC)      // 32
#define PLANE 8192            // 128 rows x 32 fp16 (64B rows)
#define OFF_B (4 * PLANE)     // A: 2 bufs x 2 planes; B: 3 bufs x 2 planes
#define SMEM_BYTES 100352     // max(gemm 80KB, epilogue C+eps staging 100KB)

__device__ __half g_w[2][128 * DK];   // fp16(32w), fp16(32w - hi); K-major

__device__ __forceinline__ uint32_t smem_u32(const void* p) {
    uint32_t a;
    asm("{ .reg .u64 t; cvta.to.shared.u64 t, %1; cvt.u32.u64 %0, t; }" : "=r"(a) : "l"(p));
    return a;
}
__device__ __forceinline__ uint32_t swz32(uint32_t r, uint32_t c) {
    return (r >> 1) * 128 + (r & 1) * 64 + (c ^ (((r >> 1) & 3) << 4));
}
__device__ __forceinline__ void cp16(uint32_t dst, const void* src) {
    asm volatile("cp.async.cg.shared.global [%0], [%1], 16;" :: "r"(dst), "l"(src));
}
__device__ __forceinline__ void ldsm4(uint32_t& r0, uint32_t& r1, uint32_t& r2,
                                      uint32_t& r3, uint32_t addr) {
    asm volatile("ldmatrix.sync.aligned.m8n8.x4.shared.b16 {%0,%1,%2,%3}, [%4];"
                 : "=r"(r0), "=r"(r1), "=r"(r2), "=r"(r3) : "r"(addr));
}
__device__ __forceinline__ void mma16816(float* c, const uint32_t* a,
                                         uint32_t b0, uint32_t b1) {
    asm volatile("mma.sync.aligned.m16n8k16.row.col.f32.f16.f16.f32 "
                 "{%0,%1,%2,%3}, {%4,%5,%6,%7}, {%8,%9}, {%0,%1,%2,%3};"
                 : "+f"(c[0]), "+f"(c[1]), "+f"(c[2]), "+f"(c[3])
                 : "r"(a[0]), "r"(a[1]), "r"(a[2]), "r"(a[3]), "r"(b0), "r"(b1));
}
__device__ __forceinline__ float softplusf(float v) {
    return fmaxf(v, 0.0f) + log1pf(expf(-fabsf(v)));
}
__device__ __forceinline__ uint32_t h2u(__half2 h) {
    union { __half2 h; uint32_t u; } v; v.h = h; return v.u;
}

__global__ void prep_weights(const float* __restrict__ wr, const float* __restrict__ wn) {
    int i = blockIdx.x * blockDim.x + threadIdx.x;    // 0 .. 128*1024-1
    int e = i >> 10, k = i & 1023;
    float v = 32.0f * ((e < NE) ? wr[e * DK + k] : wn[(e - NE) * DK + k]);
    __half h = __float2half_rn(v);
    g_w[0][i] = h;
    g_w[1][i] = __float2half_rn(v - __half2float(h));
}

__global__ __launch_bounds__(256, 2)
void router_gemm(const float* __restrict__ x, const float* __restrict__ eps,
                 float* __restrict__ out, float* __restrict__ idx_out, int write_idx)
{
    extern __shared__ char smem[];
    const uint32_t sb = smem_u32(smem);
    const int tid = threadIdx.x;
    const int lane = tid & 31, wid = tid >> 5;
    const int wm = wid & 1, wq = wid >> 1;        // warp tile 64x32 at (wm*64, wq*32)
    const int row0 = blockIdx.x * BM;

    // coalesced zero-fill of this block's output tile [128 x 64]
    {
        float4 z = make_float4(0.f, 0.f, 0.f, 0.f);
        float4* ot = (float4*)(out + (size_t)row0 * NE);
        #pragma unroll
        for (int i = 0; i < 8; ++i) ot[tid + 256 * i] = z;
    }

    // ldmatrix per-lane address pieces
    const int rA = wm * 64 + (lane & 15);
    const uint32_t rowA = (uint32_t)((rA >> 1) * 128 + (rA & 1) * 64);
    const uint32_t xorA = (uint32_t)(((rA >> 1) & 3) << 4);
    const uint32_t cbA  = (uint32_t)((lane >> 4) * 16);
    const int rB = wq * 32 + (lane & 7) + ((lane >> 4) << 3);
    const uint32_t rowB = (uint32_t)((rB >> 1) * 128 + (rB & 1) * 64);
    const uint32_t xorB = (uint32_t)(((rB >> 1) & 3) << 4);
    const uint32_t cbB  = (uint32_t)(((lane >> 3) & 1) * 16);

    // x staging: thread covers row r_x, 16 floats at float-offset h_x
    const int r_x = tid >> 1;
    const int h_x = (tid & 1) * 16;
    const float* xbase = x + (size_t)(row0 + r_x) * DK + h_x;
    const uint32_t rowX = (uint32_t)((r_x >> 1) * 128 + (r_x & 1) * 64);
    const uint32_t xorX = (uint32_t)(((r_x >> 1) & 3) << 4);
    const uint32_t swX0 = rowX + (((uint32_t)(h_x * 2) +  0) ^ xorX);
    const uint32_t swX1 = rowX + (((uint32_t)(h_x * 2) + 16) ^ xorX);

    float acc[4][4][4];
    #pragma unroll
    for (int mt = 0; mt < 4; ++mt)
        #pragma unroll
        for (int nt = 0; nt < 4; ++nt)
            #pragma unroll
            for (int q = 0; q < 4; ++q) acc[mt][nt][q] = 0.f;

    // ---- prologue: x chunk0 -> regs -> convert into A[0]; x chunk1 -> regs;
    //      B chunks 0,1 -> cp.async (two groups) ----
    float4 xr[4];
    #pragma unroll
    for (int i = 0; i < 4; ++i) xr[i] = *(const float4*)(xbase + 4 * i);
    {
        uint32_t hh[8], hl[8];
        #pragma unroll
        for (int i = 0; i < 4; ++i) {
            float4 f4 = xr[i];
            xr[i] = *(const float4*)(xbase + KC + 4 * i);
            __half2 a = __floats2half2_rn(f4.x, f4.y);
            __half2 b = __floats2half2_rn(f4.z, f4.w);
            float2 fa = __half22float2(a), fb = __half22float2(b);
            hh[2 * i]     = h2u(a);
            hh[2 * i + 1] = h2u(b);
            hl[2 * i]     = h2u(__floats2half2_rn(f4.x - fa.x, f4.y - fa.y));
            hl[2 * i + 1] = h2u(__floats2half2_rn(f4.z - fb.x, f4.w - fb.y));
        }
        *(uint4*)(smem + swX0)         = make_uint4(hh[0], hh[1], hh[2], hh[3]);
        *(uint4*)(smem + swX1)         = make_uint4(hh[4], hh[5], hh[6], hh[7]);
        *(uint4*)(smem + PLANE + swX0) = make_uint4(hl[0], hl[1], hl[2], hl[3]);
        *(uint4*)(smem + PLANE + swX1) = make_uint4(hl[4], hl[5], hl[6], hl[7]);
    }
    #pragma unroll
    for (int j = 0; j < 4; ++j) {
        const int u = tid + 256 * j;             // 0..1023
        const int s = u >> 9, rem = u & 511;
        const int n = rem >> 2, cu = (rem & 3) * 16;
        cp16(sb + OFF_B + (uint32_t)s * PLANE + swz32(n, cu), &g_w[s][n * DK + (cu >> 1)]);
    }
    asm volatile("cp.async.commit_group;" ::: "memory");
    #pragma unroll
    for (int j = 0; j < 4; ++j) {
        const int u = tid + 256 * j;
        const int s = u >> 9, rem = u & 511;
        const int n = rem >> 2, cu = (rem & 3) * 16;
        cp16(sb + OFF_B + (uint32_t)(2 + s) * PLANE + swz32(n, cu),
             &g_w[s][n * DK + KC + (cu >> 1)]);
    }
    asm volatile("cp.async.commit_group;" ::: "memory");

    int br = 0;   // B read buffer (c % 3)
    int bp = 2;   // B prefetch buffer ((c+2) % 3)

    #pragma unroll 1
    for (int c = 0; c < NCHUNK; ++c) {
        const int b = c & 1;

        // G(c) complete for THIS thread, then publish block-wide.
        asm volatile("cp.async.wait_group 1;" ::: "memory");
        __syncthreads();                         // A[b] + B[br] visible

        // ---- issue B chunk c+2 into buffer bp (consumed in c-1, pre-sync) ----
        if (c + 2 < NCHUNK) {
            const int kB = (c + 2) * KC;
            #pragma unroll
            for (int j = 0; j < 4; ++j) {
                const int u = tid + 256 * j;
                const int s = u >> 9, rem = u & 511;
                const int n = rem >> 2, cu = (rem & 3) * 16;
                cp16(sb + OFF_B + (uint32_t)(bp * 2 + s) * PLANE + swz32(n, cu),
                     &g_w[s][n * DK + kB + (cu >> 1)]);
            }
        }
        asm volatile("cp.async.commit_group;" ::: "memory");   // one group/chunk

        // ---- MMA: 3 split products over 2 k16 steps ----
        const uint32_t Ah = sb + (uint32_t)(b * 2) * PLANE;
        const uint32_t Al = Ah + PLANE;
        const uint32_t Bh = sb + OFF_B + (uint32_t)(br * 2) * PLANE;
        const uint32_t Bl = Bh + PLANE;
        #pragma unroll
        for (int ks = 0; ks < 2; ++ks) {
            const uint32_t kb = (uint32_t)(ks * 32);
            const uint32_t ca = (kb + cbA) ^ xorA;
            const uint32_t cc = (kb + cbB) ^ xorB;
            uint32_t a[4][4], bh[8], bl[8];
            #pragma unroll
            for (int mt = 0; mt < 4; ++mt)
                ldsm4(a[mt][0], a[mt][1], a[mt][2], a[mt][3], Ah + rowA + mt * 1024 + ca);
            ldsm4(bh[0], bh[1], bh[2], bh[3], Bh + rowB + cc);
            ldsm4(bh[4], bh[5], bh[6], bh[7], Bh + rowB + 1024 + cc);
            ldsm4(bl[0], bl[1], bl[2], bl[3], Bl + rowB + cc);
            ldsm4(bl[4], bl[5], bl[6], bl[7], Bl + rowB + 1024 + cc);
            #pragma unroll
            for (int mt = 0; mt < 4; ++mt)
                #pragma unroll
                for (int nt = 0; nt < 4; ++nt)
                    mma16816(acc[mt][nt], a[mt], bh[2 * nt], bh[2 * nt + 1]);
            #pragma unroll
            for (int mt = 0; mt < 4; ++mt)
                #pragma unroll
                for (int nt = 0; nt < 4; ++nt)
                    mma16816(acc[mt][nt], a[mt], bl[2 * nt], bl[2 * nt + 1]);
            #pragma unroll
            for (int mt = 0; mt < 4; ++mt)
                ldsm4(a[mt][0], a[mt][1], a[mt][2], a[mt][3], Al + rowA + mt * 1024 + ca);
            #pragma unroll
            for (int mt = 0; mt < 4; ++mt)
                #pragma unroll
                for (int nt = 0; nt < 4; ++nt)
                    mma16816(acc[mt][nt], a[mt], bh[2 * nt], bh[2 * nt + 1]);
        }

        // ---- convert x(c+1) -> A[1-b] (behind the MMA; prior reads of
        // A[1-b] were in chunk c-1's MMA, separated by this chunk's sync);
        // prefetch x(c+2) into regs ----
        if (c + 1 < NCHUNK) {
            const int k2 = ((c + 2) & (NCHUNK - 1)) * KC;   // wraps, safe
            char* An = smem + (uint32_t)((1 - b) * 2) * PLANE;
            uint32_t hh[8], hl[8];
            #pragma unroll
            for (int i = 0; i < 4; ++i) {
                float4 f4 = xr[i];
                xr[i] = *(const float4*)(xbase + k2 + 4 * i);
                __half2 a2 = __floats2half2_rn(f4.x, f4.y);
                __half2 b2 = __floats2half2_rn(f4.z, f4.w);
                float2 fa = __half22float2(a2), fb = __half22float2(b2);
                hh[2 * i]     = h2u(a2);
                hh[2 * i + 1] = h2u(b2);
                hl[2 * i]     = h2u(__floats2half2_rn(f4.x - fa.x, f4.y - fa.y));
                hl[2 * i + 1] = h2u(__floats2half2_rn(f4.z - fb.x, f4.w - fb.y));
            }
            *(uint4*)(An + swX0)         = make_uint4(hh[0], hh[1], hh[2], hh[3]);
            *(uint4*)(An + swX1)         = make_uint4(hh[4], hh[5], hh[6], hh[7]);
            *(uint4*)(An + PLANE + swX0) = make_uint4(hl[0], hl[1], hl[2], hl[3]);
            *(uint4*)(An + PLANE + swX1) = make_uint4(hl[4], hl[5], hl[6], hl[7]);
        }

        br = (br == 2) ? 0 : br + 1;
        bp = (bp == 2) ? 0 : bp + 1;
    }
    __syncthreads();

    // ---- stage C (scaled 1/32) + eps to smem, fused top-2 epilogue ----
    float* Cs = (float*)smem;                    // [128][130]
    float* Es = (float*)(smem + 66560);          // [128][66]
    {
        const float INV32 = 0.03125f;
        const int crow = wm * 64 + (lane >> 2);
        const int ccol = wq * 32 + (lane & 3) * 2;
        #pragma unroll
        for (int mt = 0; mt < 4; ++mt)
            #pragma unroll
            for (int nt = 0; nt < 4; ++nt) {
                float* p0 = Cs + (crow + mt * 16) * 130 + ccol + nt * 8;
                p0[0] = acc[mt][nt][0] * INV32; p0[1] = acc[mt][nt][1] * INV32;
                float* p1 = p0 + 8 * 130;
                p1[0] = acc[mt][nt][2] * INV32; p1[1] = acc[mt][nt][3] * INV32;
            }
        const float4* eg = (const float4*)(eps + (size_t)row0 * NE);
        #pragma unroll
        for (int i4 = 0; i4 < 8; ++i4) {
            int u = tid + 256 * i4;                 // 0..2047
            float4 v = eg[u];
            int r = u >> 4, e = (u & 15) * 4;
            float* d = Es + r * 66 + e;
            d[0] = v.x; d[1] = v.y; d[2] = v.z; d[3] = v.w;
        }
    }
    __syncthreads();

    if (tid < BM) {
        const int r = tid;
        const size_t n = (size_t)row0 + r;
        const float* lg = Cs + r * 130;
        const float* er = Es + r * 66;
        const float NEG = __int_as_float(0xff800000);
        float m1 = NEG, m2 = NEG; int i1 = 0, i2 = 0;
        #pragma unroll
        for (int e = 0; e < NE; ++e) {
            float v = lg[e] + er[e] * softplusf(lg[e + 64]);
            if (v > m1) { m2 = m1; i2 = i1; m1 = v; i1 = e; }
            else if (v > m2) { m2 = v; i2 = e; }
        }
        float ee = expf(m2 - m1);
        float inv = 1.0f / (1.0f + ee);
        out[n * NE + i1] = inv;
        out[n * NE + i2] = ee * inv;
        if (write_idx) {
            idx_out[n * 2 + 0] = (float)i1;
            idx_out[n * 2 + 1] = (float)i2;
        }
    }
}

extern "C" void kernel_launch(void* const* d_in, const int* in_sizes, int n_in,
                              void* d_out, int out_size)
{
    const float* x   = (const float*)d_in[0];
    const float* wr  = (const float*)d_in[1];
    const float* wn  = (const float*)d_in[2];
    const float* eps = (const float*)d_in[3];
    float* out = (float*)d_out;

    const int N = in_sizes[3] / NE;
    const int write_idx = (out_size >= N * NE + N * 2) ? 1 : 0;
    float* idx_out = out + (size_t)N * NE;

    prep_weights<<<(128 * DK) / 256, 256>>>(wr, wn);

    cudaFuncSetAttribute(router_gemm,
                         cudaFuncAttributeMaxDynamicSharedMemorySize, SMEM_BYTES);
    router_gemm<<<N / BM, 256, SMEM_BYTES>>>(x, eps, out, idx_out, write_idx);
}

// round 12
// speedup vs baseline: 1.6872x; 1.0785x over previous
#include <cuda_runtime.h>
#include <cuda_fp16.h>
#include <cstdint>

// TopKNoisyRouter: fused dual GEMM [N,1024]x[1024,128], fp16 2-way split
// (3 HMMA products, fp32 accum, W pre-scaled by 32). Round-9 skeleton
// (convert(c) -> wait -> sync -> issue B(c+2) -> MMA(c); A 2-buf, B 3-buf
// ring at cp.async distance 2) plus: warp-parity k-step stagger and a
// split ldsm/MMA interleave to break the post-barrier crossbar convoy,
// packed f16x2 converts + STS.128, and hoisted cp.async address math.
// 2 CTAs/SM. Fused noisy-top-2 + softmax epilogue.

#define DK 1024
#define NE 64
#define BM 128
#define KC 32
#define NCHUNK (DK / KC)      // 32
#define PLANE 8192            // 128 rows x 32 fp16 (64B rows)
#define OFF_B (4 * PLANE)     // A: 2 bufs x 2 planes; B: 3 bufs x 2 planes
#define SMEM_BYTES 100352     // max(gemm 80KB, epilogue C+eps staging 100KB)

__device__ __half g_w[2][128 * DK];   // fp16(32w), fp16(32w - hi); K-major

__device__ __forceinline__ uint32_t smem_u32(const void* p) {
    uint32_t a;
    asm("{ .reg .u64 t; cvta.to.shared.u64 t, %1; cvt.u32.u64 %0, t; }" : "=r"(a) : "l"(p));
    return a;
}
__device__ __forceinline__ uint32_t swz32(uint32_t r, uint32_t c) {
    return (r >> 1) * 128 + (r & 1) * 64 + (c ^ (((r >> 1) & 3) << 4));
}
__device__ __forceinline__ void cp16(uint32_t dst, const void* src) {
    asm volatile("cp.async.cg.shared.global [%0], [%1], 16;" :: "r"(dst), "l"(src));
}
__device__ __forceinline__ void ldsm4(uint32_t& r0, uint32_t& r1, uint32_t& r2,
                                      uint32_t& r3, uint32_t addr) {
    asm volatile("ldmatrix.sync.aligned.m8n8.x4.shared.b16 {%0,%1,%2,%3}, [%4];"
                 : "=r"(r0), "=r"(r1), "=r"(r2), "=r"(r3) : "r"(addr));
}
__device__ __forceinline__ void mma16816(float* c, const uint32_t* a,
                                         uint32_t b0, uint32_t b1) {
    asm volatile("mma.sync.aligned.m16n8k16.row.col.f32.f16.f16.f32 "
                 "{%0,%1,%2,%3}, {%4,%5,%6,%7}, {%8,%9}, {%0,%1,%2,%3};"
                 : "+f"(c[0]), "+f"(c[1]), "+f"(c[2]), "+f"(c[3])
                 : "r"(a[0]), "r"(a[1]), "r"(a[2]), "r"(a[3]), "r"(b0), "r"(b1));
}
__device__ __forceinline__ float softplusf(float v) {
    return fmaxf(v, 0.0f) + log1pf(expf(-fabsf(v)));
}
__device__ __forceinline__ uint32_t h2u(__half2 h) {
    union { __half2 h; uint32_t u; } v; v.h = h; return v.u;
}

__global__ void prep_weights(const float* __restrict__ wr, const float* __restrict__ wn) {
    int i = blockIdx.x * blockDim.x + threadIdx.x;    // 0 .. 128*1024-1
    int e = i >> 10, k = i & 1023;
    float v = 32.0f * ((e < NE) ? wr[e * DK + k] : wn[(e - NE) * DK + k]);
    __half h = __float2half_rn(v);
    g_w[0][i] = h;
    g_w[1][i] = __float2half_rn(v - __half2float(h));
}

__global__ __launch_bounds__(256, 2)
void router_gemm(const float* __restrict__ x, const float* __restrict__ eps,
                 float* __restrict__ out, float* __restrict__ idx_out, int write_idx)
{
    extern __shared__ char smem[];
    const uint32_t sb = smem_u32(smem);
    const int tid = threadIdx.x;
    const int lane = tid & 31, wid = tid >> 5;
    const int wm = wid & 1, wq = wid >> 1;        // warp tile 64x32 at (wm*64, wq*32)
    const int row0 = blockIdx.x * BM;

    // coalesced zero-fill of this block's output tile [128 x 64]
    {
        float4 z = make_float4(0.f, 0.f, 0.f, 0.f);
        float4* ot = (float4*)(out + (size_t)row0 * NE);
        #pragma unroll
        for (int i = 0; i < 8; ++i) ot[tid + 256 * i] = z;
    }

    // ldmatrix per-lane address pieces
    const int rA = wm * 64 + (lane & 15);
    const uint32_t rowA = (uint32_t)((rA >> 1) * 128 + (rA & 1) * 64);
    const uint32_t xorA = (uint32_t)(((rA >> 1) & 3) << 4);
    const uint32_t cbA  = (uint32_t)((lane >> 4) * 16);
    const int rB = wq * 32 + (lane & 7) + ((lane >> 4) << 3);
    const uint32_t rowB = (uint32_t)((rB >> 1) * 128 + (rB & 1) * 64);
    const uint32_t xorB = (uint32_t)(((rB >> 1) & 3) << 4);
    const uint32_t cbB  = (uint32_t)(((lane >> 3) & 1) * 16);
    const int ksw = wid & 1;     // k-step stagger parity

    // x staging: thread covers row r_x, 16 floats at float-offset h_x
    const int r_x = tid >> 1;
    const int h_x = (tid & 1) * 16;
    const float* xbase = x + (size_t)(row0 + r_x) * DK + h_x;
    const uint32_t rowX = (uint32_t)((r_x >> 1) * 128 + (r_x & 1) * 64);
    const uint32_t xorX = (uint32_t)(((r_x >> 1) & 3) << 4);
    const uint32_t swX0 = rowX + (((uint32_t)(h_x * 2) +  0) ^ xorX);
    const uint32_t swX1 = rowX + (((uint32_t)(h_x * 2) + 16) ^ xorX);

    // hoisted cp.async per-thread addressing (4 copies of 16B per chunk)
    uint32_t bdst[4];
    const __half* bsrc[4];
    #pragma unroll
    for (int j = 0; j < 4; ++j) {
        const int u = tid + 256 * j;             // 0..1023
        const int s = u >> 9, rem = u & 511;
        const int n = rem >> 2, cu = (rem & 3) * 16;
        bdst[j] = sb + OFF_B + (uint32_t)s * PLANE + swz32((uint32_t)n, (uint32_t)cu);
        bsrc[j] = &g_w[s][n * DK + (cu >> 1)];
    }

    float acc[4][4][4];
    #pragma unroll
    for (int mt = 0; mt < 4; ++mt)
        #pragma unroll
        for (int nt = 0; nt < 4; ++nt)
            #pragma unroll
            for (int q = 0; q < 4; ++q) acc[mt][nt][q] = 0.f;

    // ---- prologue: x chunk0 -> regs; B chunks 0,1 -> cp.async (2 groups) ----
    float4 xr[4];
    #pragma unroll
    for (int i = 0; i < 4; ++i) xr[i] = *(const float4*)(xbase + 4 * i);
    #pragma unroll
    for (int j = 0; j < 4; ++j) cp16(bdst[j], bsrc[j]);
    asm volatile("cp.async.commit_group;" ::: "memory");
    #pragma unroll
    for (int j = 0; j < 4; ++j) cp16(bdst[j] + 2 * PLANE, bsrc[j] + KC);
    asm volatile("cp.async.commit_group;" ::: "memory");

    int br = 0;   // B read buffer (c % 3)
    int bp = 2;   // B prefetch buffer ((c+2) % 3)

    #pragma unroll 1
    for (int c = 0; c < NCHUNK; ++c) {
        const int b = c & 1;
        const int kn = ((c + 1) & (NCHUNK - 1)) * KC;   // next x chunk (wraps, safe)
        char* Ab = smem + (uint32_t)(b * 2) * PLANE;

        // ---- convert x regs (chunk c) -> A[b] (packed f16x2, STS.128);
        //      prefetch next x into regs ----
        {
            uint32_t hh[8], hl[8];
            #pragma unroll
            for (int i = 0; i < 4; ++i) {
                float4 f4 = xr[i];
                xr[i] = *(const float4*)(xbase + kn + 4 * i);
                __half2 a2 = __floats2half2_rn(f4.x, f4.y);
                __half2 b2 = __floats2half2_rn(f4.z, f4.w);
                float2 fa = __half22float2(a2), fb = __half22float2(b2);
                hh[2 * i]     = h2u(a2);
                hh[2 * i + 1] = h2u(b2);
                hl[2 * i]     = h2u(__floats2half2_rn(f4.x - fa.x, f4.y - fa.y));
                hl[2 * i + 1] = h2u(__floats2half2_rn(f4.z - fb.x, f4.w - fb.y));
            }
            *(uint4*)(Ab + swX0)         = make_uint4(hh[0], hh[1], hh[2], hh[3]);
            *(uint4*)(Ab + swX1)         = make_uint4(hh[4], hh[5], hh[6], hh[7]);
            *(uint4*)(Ab + PLANE + swX0) = make_uint4(hl[0], hl[1], hl[2], hl[3]);
            *(uint4*)(Ab + PLANE + swX1) = make_uint4(hl[4], hl[5], hl[6], hl[7]);
        }

        // B group for chunk c complete for THIS thread, then publish.
        asm volatile("cp.async.wait_group 1;" ::: "memory");
        __syncthreads();                         // A[b] + B[br] visible

        // ---- issue B chunk c+2 into buffer bp (consumed in c-1, pre-sync);
        //      commit ALWAYS (empty on tail) to keep accounting exact ----
        if (c + 2 < NCHUNK) {
            const int kB = (c + 2) * KC;
            const uint32_t bb = (uint32_t)(bp * 2) * PLANE;
            #pragma unroll
            for (int j = 0; j < 4; ++j) cp16(bdst[j] + bb, bsrc[j] + kB);
        }
        asm volatile("cp.async.commit_group;" ::: "memory");

        // ---- MMA: 3 split products over 2 k16 steps, staggered by warp
        //      parity; ldsm groups interleaved with MMA groups ----
        const uint32_t Ah = sb + (uint32_t)(b * 2) * PLANE;
        const uint32_t Al = Ah + PLANE;
        const uint32_t Bh = sb + OFF_B + (uint32_t)(br * 2) * PLANE;
        const uint32_t Bl = Bh + PLANE;
        #pragma unroll
        for (int t = 0; t < 2; ++t) {
            const int ks = t ^ ksw;              // even warps 0,1; odd 1,0
            const uint32_t kb = (uint32_t)(ks * 32);
            const uint32_t ca = (kb + cbA) ^ xorA;
            const uint32_t cc = (kb + cbB) ^ xorB;
            uint32_t a[4][4], bh[8], bl[8];
            // group 1: A-hi + B-hi, then hh product
            #pragma unroll
            for (int mt = 0; mt < 4; ++mt)
                ldsm4(a[mt][0], a[mt][1], a[mt][2], a[mt][3], Ah + rowA + mt * 1024 + ca);
            ldsm4(bh[0], bh[1], bh[2], bh[3], Bh + rowB + cc);
            ldsm4(bh[4], bh[5], bh[6], bh[7], Bh + rowB + 1024 + cc);
            #pragma unroll
            for (int mt = 0; mt < 4; ++mt)
                #pragma unroll
                for (int nt = 0; nt < 4; ++nt)
                    mma16816(acc[mt][nt], a[mt], bh[2 * nt], bh[2 * nt + 1]);
            // group 2: B-lo, then hl product
            ldsm4(bl[0], bl[1], bl[2], bl[3], Bl + rowB + cc);
            ldsm4(bl[4], bl[5], bl[6], bl[7], Bl + rowB + 1024 + cc);
            #pragma unroll
            for (int mt = 0; mt < 4; ++mt)
                #pragma unroll
                for (int nt = 0; nt < 4; ++nt)
                    mma16816(acc[mt][nt], a[mt], bl[2 * nt], bl[2 * nt + 1]);
            // group 3: A-lo, then lh product
            #pragma unroll
            for (int mt = 0; mt < 4; ++mt)
                ldsm4(a[mt][0], a[mt][1], a[mt][2], a[mt][3], Al + rowA + mt * 1024 + ca);
            #pragma unroll
            for (int mt = 0; mt < 4; ++mt)
                #pragma unroll
                for (int nt = 0; nt < 4; ++nt)
                    mma16816(acc[mt][nt], a[mt], bh[2 * nt], bh[2 * nt + 1]);
        }

        br = (br == 2) ? 0 : br + 1;
        bp = (bp == 2) ? 0 : bp + 1;
    }
    __syncthreads();

    // ---- stage C (scaled 1/32) + eps to smem, fused top-2 epilogue ----
    float* Cs = (float*)smem;                    // [128][130]
    float* Es = (float*)(smem + 66560);          // [128][66]
    {
        const float INV32 = 0.03125f;
        const int crow = wm * 64 + (lane >> 2);
        const int ccol = wq * 32 + (lane & 3) * 2;
        #pragma unroll
        for (int mt = 0; mt < 4; ++mt)
            #pragma unroll
            for (int nt = 0; nt < 4; ++nt) {
                float* p0 = Cs + (crow + mt * 16) * 130 + ccol + nt * 8;
                p0[0] = acc[mt][nt][0] * INV32; p0[1] = acc[mt][nt][1] * INV32;
                float* p1 = p0 + 8 * 130;
                p1[0] = acc[mt][nt][2] * INV32; p1[1] = acc[mt][nt][3] * INV32;
            }
        const float4* eg = (const float4*)(eps + (size_t)row0 * NE);
        #pragma unroll
        for (int i4 = 0; i4 < 8; ++i4) {
            int u = tid + 256 * i4;                 // 0..2047
            float4 v = eg[u];
            int r = u >> 4, e = (u & 15) * 4;
            float* d = Es + r * 66 + e;
            d[0] = v.x; d[1] = v.y; d[2] = v.z; d[3] = v.w;
        }
    }
    __syncthreads();

    if (tid < BM) {
        const int r = tid;
        const size_t n = (size_t)row0 + r;
        const float* lg = Cs + r * 130;
        const float* er = Es + r * 66;
        const float NEG = __int_as_float(0xff800000);
        float m1 = NEG, m2 = NEG; int i1 = 0, i2 = 0;
        #pragma unroll
        for (int e = 0; e < NE; ++e) {
            float v = lg[e] + er[e] * softplusf(lg[e + 64]);
            if (v > m1) { m2 = m1; i2 = i1; m1 = v; i1 = e; }
            else if (v > m2) { m2 = v; i2 = e; }
        }
        float ee = expf(m2 - m1);
        float inv = 1.0f / (1.0f + ee);
        out[n * NE + i1] = inv;
        out[n * NE + i2] = ee * inv;
        if (write_idx) {
            idx_out[n * 2 + 0] = (float)i1;
            idx_out[n * 2 + 1] = (float)i2;
        }
    }
}

extern "C" void kernel_launch(void* const* d_in, const int* in_sizes, int n_in,
                              void* d_out, int out_size)
{
    const float* x   = (const float*)d_in[0];
    const float* wr  = (const float*)d_in[1];
    const float* wn  = (const float*)d_in[2];
    const float* eps = (const float*)d_in[3];
    float* out = (float*)d_out;

    const int N = in_sizes[3] / NE;
    const int write_idx = (out_size >= N * NE + N * 2) ? 1 : 0;
    float* idx_out = out + (size_t)N * NE;

    prep_weights<<<(128 * DK) / 256, 256>>>(wr, wn);

    cudaFuncSetAttribute(router_gemm,
                         cudaFuncAttributeMaxDynamicSharedMemorySize, SMEM_BYTES);
    router_gemm<<<N / BM, 256, SMEM_BYTES>>>(x, eps, out, idx_out, write_idx);
}